// round 5
// baseline (speedup 1.0000x reference)
#include <cuda_runtime.h>
#include <math.h>
#include <stdint.h>

// ---------------- problem constants ----------------
#define BB      8
#define TT      4096
#define DD      512
#define QQ      4
#define KK_CB   1024
#define KER     5
#define TOUT    2048
#define NTOK    32768
#define NELEM   (NTOK * DD)              // 16777216
#define Y_SZ    (BB * TOUT * DD)         // 8388608
#define QO_SZ   NELEM
#define IDX_SZ  (QQ * NTOK)
#define LOSS_OFF (Y_SZ + QO_SZ + IDX_SZ)
#define PAD     132

// ---------------- persistent scratch ----------------
__device__ float  g_residual[NELEM];     // 64 MB
__device__ float  g_cnorm[QQ * KK_CB];
__device__ int    g_idx[QQ * NTOK];
__device__ double g_loss;

// ---------------- codebook norms (+loss reset) ----------------
__global__ void cnorm_kernel(const float* __restrict__ cb) {
    if (blockIdx.x == 0 && threadIdx.x == 0) g_loss = 0.0;
    int w    = (blockIdx.x * blockDim.x + threadIdx.x) >> 5;
    int lane = threadIdx.x & 31;
    if (w >= QQ * KK_CB) return;
    const float* c = cb + (size_t)w * DD;
    float s = 0.f;
    #pragma unroll
    for (int d = lane; d < DD; d += 32) { float v = c[d]; s += v * v; }
    #pragma unroll
    for (int o = 16; o > 0; o >>= 1) s += __shfl_down_sync(0xffffffffu, s, o);
    if (lane == 0) g_cnorm[w] = s;
}

// ---------------- fused VQ stage: pipelined distance GEMM + argmin + update ----------------
// dist(token,k) = ||c_k||^2 - 2 * r . c_k
// Tile 128x128, K-chunk 16, 8x8 microtile, 256 thr, double-buffered smem + reg prefetch.
__global__ __launch_bounds__(256, 2)
void vq_stage_kernel(const float* __restrict__ x,
                     const float* __restrict__ cb_stage,   // [1024,512] fp32
                     float* __restrict__ quant,            // written only when stage==QQ-1
                     int stage) {
    __shared__ union {
        struct { float A[2][16][PAD]; float B[2][16][PAD]; } db;   // 33792 B
        struct { float d[128][17]; int k[128][17]; } red;          // 17408 B
    } sm;
    __shared__ int   s_bk[128];
    __shared__ float s_l[8];

    const float* __restrict__ Asrc = (stage == 0) ? x : g_residual;
    const float* __restrict__ cn = g_cnorm + stage * KK_CB;

    int t  = threadIdx.x;
    int tx = t & 15, ty = t >> 4;
    int row0 = blockIdx.x * 128;

    float bestd[8];
    int   bestk[8];
    #pragma unroll
    for (int i = 0; i < 8; i++) { bestd[i] = 3.4e38f; bestk[i] = 0; }

    float acc[8][8];
    #pragma unroll
    for (int i = 0; i < 8; i++)
        #pragma unroll
        for (int j = 0; j < 8; j++) acc[i][j] = 0.f;

    // loader lane mapping (shared by prefetch + STS)
    int lr0 = (t + 0)   >> 2, lc0 = (t + 0)   & 3;
    int lr1 = (t + 256) >> 2, lc1 = (t + 256) & 3;

    float4 pa[2], pb[2];
    // prologue: chunk 0 (nt=0, kc=0)
    pa[0] = *(const float4*)(Asrc + (size_t)(row0 + lr0) * DD + 4 * lc0);
    pa[1] = *(const float4*)(Asrc + (size_t)(row0 + lr1) * DD + 4 * lc1);
    pb[0] = *(const float4*)(cb_stage + (size_t)lr0 * DD + 4 * lc0);
    pb[1] = *(const float4*)(cb_stage + (size_t)lr1 * DD + 4 * lc1);

    // 256 chunks: ch = nt*32 + kc
    for (int ch = 0; ch < 256; ++ch) {
        int buf = ch & 1;
        // store prefetched chunk into buf (A transposed, B transposed)
        sm.db.A[buf][4*lc0+0][lr0] = pa[0].x; sm.db.A[buf][4*lc0+1][lr0] = pa[0].y;
        sm.db.A[buf][4*lc0+2][lr0] = pa[0].z; sm.db.A[buf][4*lc0+3][lr0] = pa[0].w;
        sm.db.A[buf][4*lc1+0][lr1] = pa[1].x; sm.db.A[buf][4*lc1+1][lr1] = pa[1].y;
        sm.db.A[buf][4*lc1+2][lr1] = pa[1].z; sm.db.A[buf][4*lc1+3][lr1] = pa[1].w;
        sm.db.B[buf][4*lc0+0][lr0] = pb[0].x; sm.db.B[buf][4*lc0+1][lr0] = pb[0].y;
        sm.db.B[buf][4*lc0+2][lr0] = pb[0].z; sm.db.B[buf][4*lc0+3][lr0] = pb[0].w;
        sm.db.B[buf][4*lc1+0][lr1] = pb[1].x; sm.db.B[buf][4*lc1+1][lr1] = pb[1].y;
        sm.db.B[buf][4*lc1+2][lr1] = pb[1].z; sm.db.B[buf][4*lc1+3][lr1] = pb[1].w;
        __syncthreads();

        // prefetch chunk ch+1
        if (ch < 255) {
            int nch = ch + 1;
            int nnt = nch >> 5, nkc = nch & 31;
            const float* Bb = cb_stage + (size_t)nnt * 128 * DD + nkc * 16;
            const float* Ab = Asrc + (size_t)row0 * DD + nkc * 16;
            pa[0] = *(const float4*)(Ab + (size_t)lr0 * DD + 4 * lc0);
            pa[1] = *(const float4*)(Ab + (size_t)lr1 * DD + 4 * lc1);
            pb[0] = *(const float4*)(Bb + (size_t)lr0 * DD + 4 * lc0);
            pb[1] = *(const float4*)(Bb + (size_t)lr1 * DD + 4 * lc1);
        }

        // compute on buf
        #pragma unroll
        for (int kk = 0; kk < 16; ++kk) {
            float a[8], b[8];
            *(float4*)(a)     = *(const float4*)&sm.db.A[buf][kk][ty * 8];
            *(float4*)(a + 4) = *(const float4*)&sm.db.A[buf][kk][ty * 8 + 4];
            *(float4*)(b)     = *(const float4*)&sm.db.B[buf][kk][tx * 8];
            *(float4*)(b + 4) = *(const float4*)&sm.db.B[buf][kk][tx * 8 + 4];
            #pragma unroll
            for (int i = 0; i < 8; i++)
                #pragma unroll
                for (int j = 0; j < 8; j++) acc[i][j] += a[i] * b[j];
        }

        // end of a code tile: fold argmin, reset acc
        if ((ch & 31) == 31) {
            int nt = ch >> 5;
            #pragma unroll
            for (int i = 0; i < 8; i++) {
                #pragma unroll
                for (int j = 0; j < 8; j++) {
                    int col = nt * 128 + tx * 8 + j;
                    float d = __ldg(cn + col) - 2.0f * acc[i][j];
                    if (d < bestd[i]) { bestd[i] = d; bestk[i] = col; }
                    acc[i][j] = 0.f;
                }
            }
        }
        __syncthreads();
    }

    // ---- cross-thread argmin reduction (reuse smem union) ----
    #pragma unroll
    for (int i = 0; i < 8; i++) { sm.red.d[ty*8+i][tx] = bestd[i]; sm.red.k[ty*8+i][tx] = bestk[i]; }
    __syncthreads();
    if (t < 128) {
        float bd = sm.red.d[t][0]; int bk = sm.red.k[t][0];
        #pragma unroll
        for (int j = 1; j < 16; j++) {
            float d = sm.red.d[t][j]; int k = sm.red.k[t][j];
            if (d < bd || (d == bd && k < bk)) { bd = d; bk = k; }
        }
        g_idx[stage * NTOK + row0 + t] = bk;
        s_bk[t] = bk;
    }
    __syncthreads();

    // ---- fused update: residual -= q ; loss ; (stage 3) quant = x - residual_new ----
    const float4* src4 = (const float4*)Asrc + (size_t)row0 * 128;
    float4*       res4 = (float4*)g_residual + (size_t)row0 * 128;
    const float4* cb4  = (const float4*)cb_stage;
    const float4* x4   = (const float4*)x + (size_t)row0 * 128;
    float4*       q4   = (float4*)quant + (size_t)row0 * 128;

    float lsum = 0.f;
    #pragma unroll 4
    for (int e = t; e < 128 * 128; e += 256) {
        int row = e >> 7, d4 = e & 127;
        int k = s_bk[row];
        float4 r = src4[e];
        float4 q = cb4[(size_t)k * 128 + d4];
        float nx = r.x - q.x, ny = r.y - q.y, nz = r.z - q.z, nw = r.w - q.w;
        lsum += nx * nx + ny * ny + nz * nz + nw * nw;
        res4[e] = make_float4(nx, ny, nz, nw);
        if (stage == QQ - 1) {
            float4 xv = x4[e];
            q4[e] = make_float4(xv.x - nx, xv.y - ny, xv.z - nz, xv.w - nw);
        }
    }
    #pragma unroll
    for (int o = 16; o > 0; o >>= 1) lsum += __shfl_down_sync(0xffffffffu, lsum, o);
    if ((t & 31) == 0) s_l[t >> 5] = lsum;
    __syncthreads();
    if (t == 0) {
        float s = 0.f;
        #pragma unroll
        for (int i = 0; i < 8; i++) s += s_l[i];
        atomicAdd(&g_loss, (double)s);
    }
}

// ---------------- conv1d (stride 2, SAME, pad_lo=1) + exact GELU, pipelined ----------------
// GEMM: out[16384,512] = patches[16384, 5*512] x W[5*512, 512]
__global__ __launch_bounds__(256, 2)
void conv_gelu_kernel(const float* __restrict__ quant,
                      const float* __restrict__ W,
                      float* __restrict__ y) {
    __shared__ struct { float A[2][16][PAD]; float B[2][16][PAD]; } sm;

    int t  = threadIdx.x;
    int tx = t & 15, ty = t >> 4;
    int mrow0 = blockIdx.x * 128;
    int ncol0 = blockIdx.y * 128;

    float acc[8][8];
    #pragma unroll
    for (int i = 0; i < 8; i++)
        #pragma unroll
        for (int j = 0; j < 8; j++) acc[i][j] = 0.f;

    // loader mapping: A transposed scatter, B contiguous rows
    int lr0 = (t + 0)   >> 2, lc0 = (t + 0)   & 3;
    int lr1 = (t + 256) >> 2, lc1 = (t + 256) & 3;
    int ar0 = mrow0 + lr0, ab0 = ar0 >> 11, at0 = ar0 & (TOUT - 1);
    int ar1 = mrow0 + lr1, ab1 = ar1 >> 11, at1 = ar1 & (TOUT - 1);
    int bc0 = (t + 0)   >> 5, bq0 = (t + 0)   & 31;   // B row (ci), col-group
    int bc1 = (t + 256) >> 5, bq1 = (t + 256) & 31;

    float4 pa[2], pb[2];
    // prologue: chunk 0 (kk=0, c0=0)
    {
        int tin0 = 2 * at0 - 1, tin1 = 2 * at1 - 1;
        pa[0] = make_float4(0.f,0.f,0.f,0.f);
        pa[1] = make_float4(0.f,0.f,0.f,0.f);
        if ((unsigned)tin0 < (unsigned)TT)
            pa[0] = *(const float4*)(quant + ((size_t)ab0 * TT + tin0) * DD + 4 * lc0);
        if ((unsigned)tin1 < (unsigned)TT)
            pa[1] = *(const float4*)(quant + ((size_t)ab1 * TT + tin1) * DD + 4 * lc1);
        pb[0] = *(const float4*)(W + (size_t)bc0 * DD + ncol0 + bq0 * 4);
        pb[1] = *(const float4*)(W + (size_t)bc1 * DD + ncol0 + bq1 * 4);
    }

    // 160 chunks: ch = kk*32 + kc  (kc selects c0 = kc*16)
    for (int ch = 0; ch < 160; ++ch) {
        int buf = ch & 1;
        sm.A[buf][4*lc0+0][lr0] = pa[0].x; sm.A[buf][4*lc0+1][lr0] = pa[0].y;
        sm.A[buf][4*lc0+2][lr0] = pa[0].z; sm.A[buf][4*lc0+3][lr0] = pa[0].w;
        sm.A[buf][4*lc1+0][lr1] = pa[1].x; sm.A[buf][4*lc1+1][lr1] = pa[1].y;
        sm.A[buf][4*lc1+2][lr1] = pa[1].z; sm.A[buf][4*lc1+3][lr1] = pa[1].w;
        *(float4*)&sm.B[buf][bc0][bq0 * 4] = pb[0];
        *(float4*)&sm.B[buf][bc1][bq1 * 4] = pb[1];
        __syncthreads();

        if (ch < 159) {
            int nch = ch + 1;
            int kk = nch >> 5, c0 = (nch & 31) * 16;
            int tin0 = 2 * at0 + kk - 1, tin1 = 2 * at1 + kk - 1;
            pa[0] = make_float4(0.f,0.f,0.f,0.f);
            pa[1] = make_float4(0.f,0.f,0.f,0.f);
            if ((unsigned)tin0 < (unsigned)TT)
                pa[0] = *(const float4*)(quant + ((size_t)ab0 * TT + tin0) * DD + c0 + 4 * lc0);
            if ((unsigned)tin1 < (unsigned)TT)
                pa[1] = *(const float4*)(quant + ((size_t)ab1 * TT + tin1) * DD + c0 + 4 * lc1);
            const float* Wk = W + (size_t)kk * DD * DD + (size_t)c0 * DD;
            pb[0] = *(const float4*)(Wk + (size_t)bc0 * DD + ncol0 + bq0 * 4);
            pb[1] = *(const float4*)(Wk + (size_t)bc1 * DD + ncol0 + bq1 * 4);
        }

        #pragma unroll
        for (int kki = 0; kki < 16; ++kki) {
            float a[8], b[8];
            *(float4*)(a)     = *(const float4*)&sm.A[buf][kki][ty * 8];
            *(float4*)(a + 4) = *(const float4*)&sm.A[buf][kki][ty * 8 + 4];
            *(float4*)(b)     = *(const float4*)&sm.B[buf][kki][tx * 8];
            *(float4*)(b + 4) = *(const float4*)&sm.B[buf][kki][tx * 8 + 4];
            #pragma unroll
            for (int i = 0; i < 8; i++)
                #pragma unroll
                for (int j = 0; j < 8; j++) acc[i][j] += a[i] * b[j];
        }
        __syncthreads();
    }

    #pragma unroll
    for (int i = 0; i < 8; i++) {
        int row = mrow0 + ty * 8 + i;
        #pragma unroll
        for (int j = 0; j < 8; j++) {
            int co = ncol0 + tx * 8 + j;
            float v = acc[i][j];
            float g = 0.5f * v * (1.0f + erff(v * 0.70710678118654752f));
            y[(size_t)row * DD + co] = g;
        }
    }
}

// ---------------- indices (as float) + loss ----------------
__global__ void finalize_kernel(float* __restrict__ out) {
    int i = blockIdx.x * blockDim.x + threadIdx.x;
    if (i < IDX_SZ) out[Y_SZ + QO_SZ + i] = (float)g_idx[i];
    if (i == 0)     out[LOSS_OFF] = (float)(0.25 * g_loss / (double)NELEM);
}

// ---------------- launch ----------------
extern "C" void kernel_launch(void* const* d_in, const int* in_sizes, int n_in,
                              void* d_out, int out_size) {
    const float* x  = (const float*)d_in[0];
    const float* cb = (const float*)d_in[1];
    const float* w  = (const float*)d_in[2];
    float* out   = (float*)d_out;
    float* y     = out;
    float* quant = out + Y_SZ;

    cnorm_kernel<<<(QQ * KK_CB * 32 + 255) / 256, 256>>>(cb);
    for (int s = 0; s < QQ; ++s)
        vq_stage_kernel<<<NTOK / 128, 256>>>(x, cb + (size_t)s * KK_CB * DD, quant, s);
    conv_gelu_kernel<<<dim3(BB * TOUT / 128, DD / 128), 256>>>(quant, w, y);
    finalize_kernel<<<(IDX_SZ + 255) / 256, 256>>>(out);
}